// round 14
// baseline (speedup 1.0000x reference)
#include <cuda_runtime.h>

// Problem constants (fixed by the reference)
static constexpr int       BS    = 64;
static constexpr int       KP1   = 8193;        // K + 1
static constexpr int       FEAT  = 128;
static constexpr long long NDATA = 1000000LL;
static constexpr float     TINV  = 1.0f / 0.07f;

// d_out layout: out_s | out_t | mem_s_new | mem_t_new  (all float32)
static constexpr long long PER       = (long long)BS * KP1;        // 524,352
static constexpr long long OUT_S_OFF = 0;
static constexpr long long OUT_T_OFF = PER;
static constexpr long long MEM_S_OFF = 2 * PER;
static constexpr long long MEM_T_OFF = MEM_S_OFF + NDATA * FEAT;

static constexpr int CC_BLOCKS    = 2368;       // copy_compute grid
static constexpr int ENT_CAP      = 8;          // bucket capacity per row
static constexpr int OVF_CAP      = 8192;
static constexpr int SCALE_BLOCKS = 513;        // epilogue scale blocks

// g_first word encoding:  count[31:20] | b[19:14] | (k+1)[13:0]
//   count: matches for this row (saturating use, capped at ENT_CAP on read)
//   (k+1): 1..8193 fits 14 bits; 0 in low 20 bits + count 0 => word 0 = empty
// Bucket entries (slots 1..ENT_CAP-1) use the same (b<<14)|(k+1) encoding.
static constexpr int      CNT_SHIFT = 20;
static constexpr int      B_SHIFT   = 14;
static constexpr unsigned KF_MASK   = (1u << B_SHIFT) - 1u;       // 0x3FFF
static constexpr unsigned ENT_MASK  = (1u << CNT_SHIFT) - 1u;     // 0xFFFFF
static_assert(KP1 <= (int)KF_MASK, "k+1 field too narrow");
static_assert(BS - 1 < (1 << (CNT_SHIFT - B_SHIFT)), "b field too narrow");

__device__ __forceinline__ unsigned enc_entry(unsigned b, unsigned k) {
    return (b << B_SHIFT) | (k + 1u);
}

// Scratch (no device allocations allowed). g_first is self-cleaning: zero at
// module load, re-zeroed by k_copy_compute after consumption each run.
__device__ unsigned g_first[NDATA];             // packed count|entry0
__device__ unsigned g_entries[NDATA * ENT_CAP]; // extra entries (slots 1..7)
__device__ unsigned g_ovf[OVF_CAP];             // overflow: flat sample index i
__device__ unsigned g_ovf_n;                    // reset by k_inv each run
__device__ double   g_sum[2];                   // Z sums (zeroed by k_build)
__device__ float    g_inv[2];                   // final scale factors

// JAX without x64 downcasts the reference's int64 indices to int32.
// Detect from first sample_idx words (true i64 values < 2^31 have zero odd words).
__device__ __forceinline__ bool detect_i64(const int* __restrict__ w) {
    return (w[1] == 0) && (w[3] == 0) && (w[5] == 0) && (w[7] == 0);
}
__device__ __forceinline__ long long load_index(const void* p, long long i, bool i64) {
    return i64 ? ((const long long*)p)[i]
               : (long long)((const int*)p)[i];
}

// Shared dot helper so main and overflow paths are bitwise identical.
__device__ __forceinline__ void dot2_reduce(const float4 vs, const float4 vt,
                                            const float4 ft, const float4 fs,
                                            float& dt, float& ds)
{
    dt = vs.x * ft.x + vs.y * ft.y + vs.z * ft.z + vs.w * ft.w;
    ds = vt.x * fs.x + vt.y * fs.y + vt.z * fs.z + vt.w * fs.w;
    #pragma unroll
    for (int o = 16; o; o >>= 1) {
        dt += __shfl_xor_sync(0xffffffffu, dt, o);
        ds += __shfl_xor_sync(0xffffffffu, ds, o);
    }
}
__device__ __forceinline__ float contrast_val(float d) {
    return __expf(fminf(d * TINV, 50.0f));
}

// Process all matches for one row. w = packed g_first word (count + entry0),
// so the dominant single-match case needs NO second index load. Z accumulates
// on lane 0 only (block reduce reads lane 0's copy).
__device__ __forceinline__ void process_row(
    long long row, unsigned w,
    const float4 vs, const float4 vt,
    const float4* __restrict__ feat_s4, const float4* __restrict__ feat_t4,
    float* __restrict__ out, int lane, double& acc_s, double& acc_t)
{
    unsigned c = w >> CNT_SHIFT;
    c = c < ENT_CAP ? c : ENT_CAP;
    for (unsigned e = 0; e < c; e++) {
        const unsigned ent = (e == 0) ? (w & ENT_MASK)
                                      : g_entries[row * ENT_CAP + e];
        const unsigned b = ent >> B_SHIFT;
        const unsigned k = (ent & KF_MASK) - 1u;
        const float4 ft = feat_t4[b * 32 + lane];
        const float4 fs = feat_s4[b * 32 + lane];
        float dt, ds;
        dot2_reduce(vs, vt, ft, fs, dt, ds);
        const float et = contrast_val(dt);
        const float es = contrast_val(ds);
        if (lane == 0) {
            acc_t += (double)et;
            acc_s += (double)es;
            const long long off = (long long)b * KP1 + k;
            out[OUT_T_OFF + off] = et;
            out[OUT_S_OFF + off] = es;
        }
    }
}

// ---------------------------------------------------------------------------
// Build inverted index. atomicAdd on the count field returns the slot; the
// FIRST arrival also sets the entry bits via atomicOr (disjoint fields;
// k_build completes before any consumer runs). Slots 1..ENT_CAP-1 go to the
// bucket; beyond that, the overflow list. Also zeroes g_sum for this run.
// ---------------------------------------------------------------------------
__global__ void __launch_bounds__(256)
k_build(const void* __restrict__ sample_idx)
{
    if (blockIdx.x == 0 && threadIdx.x == 0) { g_sum[0] = 0.0; g_sum[1] = 0.0; }
    const bool i64 = detect_i64((const int*)sample_idx);
    const long long i = (long long)blockIdx.x * blockDim.x + threadIdx.x;
    if (i >= PER) return;
    const unsigned b = (unsigned)i / (unsigned)KP1;
    const unsigned k = (unsigned)i % (unsigned)KP1;
    const long long r = load_index(sample_idx, i, i64);
    const unsigned old  = atomicAdd(&g_first[r], 1u << CNT_SHIFT);
    const unsigned slot = old >> CNT_SHIFT;
    if (slot == 0) {
        atomicOr(&g_first[r], enc_entry(b, k));
    } else if (slot < ENT_CAP) {
        g_entries[r * ENT_CAP + slot] = enc_entry(b, k);
    } else {
        const unsigned o = atomicAdd(&g_ovf_n, 1u);
        if (o < OVF_CAP) g_ovf[o] = (unsigned)i;
    }
}

// ---------------------------------------------------------------------------
// Copy + contrast + Z-sum, fused. Adjacent 2-row flat batch (R13 structure):
// 4 stream float4s + 2 adjacent g_first words per iteration, all issued
// before stores/match work. The packed word supplies count AND entry0, so
// single-match rows (77% of matched) skip the bucket load entirely.
// g_first is zeroed after consumption (self-cleaning for the next run).
// ---------------------------------------------------------------------------
__global__ void __launch_bounds__(256)
k_copy_compute(const float4* __restrict__ mem_s4, const float4* __restrict__ mem_t4,
               float4* __restrict__ dst_s4, float4* __restrict__ dst_t4,
               const float4* __restrict__ feat_s4, const float4* __restrict__ feat_t4,
               float* __restrict__ out)
{
    const int lane = threadIdx.x & 31;
    const int warp = threadIdx.x >> 5;
    const long long warpsTotal = (long long)CC_BLOCKS * 8;          // 18,944
    const long long pairStride = 2 * warpsTotal;
    const long long w0 = (long long)blockIdx.x * 8 + warp;

    double acc_s = 0.0, acc_t = 0.0;            // meaningful on lane 0

    for (long long rowA = w0 * 2; rowA < NDATA; rowA += pairStride) {
        const long long rowB = rowA + 1;
        const bool hasB = (rowB < NDATA);

        // Flat load batch: 4 stream float4s + 2 adjacent packed index words
        const long long baseA = rowA * 32 + lane;
        const float4 vsA = mem_s4[baseA];
        const float4 vtA = mem_t4[baseA];
        float4 vsB, vtB;
        long long baseB = 0;
        if (hasB) {
            baseB = rowB * 32 + lane;
            vsB = mem_s4[baseB];
            vtB = mem_t4[baseB];
        }
        const unsigned wA = g_first[rowA];
        const unsigned wB = hasB ? g_first[rowB] : 0u;

        // Stores
        dst_s4[baseA] = vsA;
        dst_t4[baseA] = vtA;
        if (hasB) {
            dst_s4[baseB] = vsB;
            dst_t4[baseB] = vtB;
        }

        // Self-clean for next run (adjacent words -> one sector)
        if (lane == 0) {
            if (wA) g_first[rowA] = 0u;
            if (wB) g_first[rowB] = 0u;
        }

        // Match work
        if (wA) process_row(rowA, wA, vsA, vtA, feat_s4, feat_t4, out, lane, acc_s, acc_t);
        if (wB) process_row(rowB, wB, vsB, vtB, feat_s4, feat_t4, out, lane, acc_s, acc_t);
    }

    // Block reduce (lane 0 values), then 2 atomics/block
    __shared__ double sh_s[8], sh_t[8];
    if (lane == 0) { sh_s[warp] = acc_s; sh_t[warp] = acc_t; }
    __syncthreads();
    if (threadIdx.x == 0) {
        double ts = 0.0, tt = 0.0;
        #pragma unroll
        for (int i = 0; i < 8; i++) { ts += sh_s[i]; tt += sh_t[i]; }
        atomicAdd(&g_sum[0], ts);
        atomicAdd(&g_sum[1], tt);
    }
}

// ---------------------------------------------------------------------------
// Inv: one warp. Handle the (almost always zero) overflow entries with
// bitwise-identical math, compute scale factors, reset overflow cursor.
// inv = PER / (sum * N_DATA)
// ---------------------------------------------------------------------------
__global__ void __launch_bounds__(32)
k_inv(const float4* __restrict__ mem_s4, const float4* __restrict__ mem_t4,
      const float4* __restrict__ feat_s4, const float4* __restrict__ feat_t4,
      const void* __restrict__ sample_idx, float* __restrict__ out)
{
    const int lane = threadIdx.x;
    double os = 0.0, ot = 0.0;                  // meaningful on lane 0
    const unsigned n = g_ovf_n < OVF_CAP ? g_ovf_n : OVF_CAP;
    if (n) {
        const bool i64 = detect_i64((const int*)sample_idx);
        for (unsigned e = 0; e < n; e++) {
            const long long i = (long long)g_ovf[e];
            const unsigned b = (unsigned)i / (unsigned)KP1;
            const unsigned k = (unsigned)i % (unsigned)KP1;
            const long long row = load_index(sample_idx, i, i64);
            const float4 vs = mem_s4[row * 32 + lane];
            const float4 vt = mem_t4[row * 32 + lane];
            const float4 ft = feat_t4[b * 32 + lane];
            const float4 fs = feat_s4[b * 32 + lane];
            float dt, ds;
            dot2_reduce(vs, vt, ft, fs, dt, ds);
            const float et = contrast_val(dt);
            const float es = contrast_val(ds);
            if (lane == 0) {
                ot += (double)et; os += (double)es;
                const long long off = (long long)b * KP1 + k;
                out[OUT_T_OFF + off] = et;
                out[OUT_S_OFF + off] = es;
            }
        }
    }
    if (lane == 0) {
        const double sum_s = g_sum[0] + os;
        const double sum_t = g_sum[1] + ot;
        g_inv[0] = (float)((double)PER / (sum_s * (double)NDATA));
        g_inv[1] = (float)((double)PER / (sum_t * (double)NDATA));
        g_ovf_n = 0u;                           // reset for next run
    }
}

// ---------------------------------------------------------------------------
// Epilogue: scale (blocks [0, SCALE_BLOCKS), grid-stride ~2 float4/thread)
// + momentum update (last 128 blocks).
// Update: reads ORIGINAL bank, overwrites the copied row in d_out.
// ---------------------------------------------------------------------------
__global__ void __launch_bounds__(256)
k_epilogue(const float* __restrict__ mem_s, const float* __restrict__ mem_t,
           const float* __restrict__ feat_s, const float* __restrict__ feat_t,
           const void*  __restrict__ idx, float* __restrict__ out)
{
    if (blockIdx.x < SCALE_BLOCKS) {
        float4* outv = (float4*)out;
        const long long n4 = 2 * PER / 4;                   // 262,176
        const long long stride = (long long)SCALE_BLOCKS * 256;
        for (long long i = (long long)blockIdx.x * 256 + threadIdx.x;
             i < n4; i += stride) {
            const float inv = g_inv[(i >= PER / 4) ? 1 : 0];
            float4 v = outv[i];
            v.x *= inv; v.y *= inv; v.z *= inv; v.w *= inv;
            outv[i] = v;
        }
        return;
    }

    // Update: 128 work blocks, threads 0..127 active
    const int ub = blockIdx.x - SCALE_BLOCKS;     // [0, 128)
    const int t  = threadIdx.x;
    __shared__ float ws[4];
    if (t < 128) {
        const bool i64 = detect_i64((const int*)idx);
        const int bank = ub >> 6;                 // 0 = s-bank, 1 = t-bank
        const int b    = ub & 63;

        const float* __restrict__ mem  = bank ? mem_t  : mem_s;
        const float* __restrict__ feat = bank ? feat_t : feat_s;
        float* __restrict__ dst = out + (bank ? MEM_T_OFF : MEM_S_OFF);

        const long long row = load_index(idx, b, i64);
        const float v = mem[row * FEAT + t] * 0.5f + feat[(long long)b * FEAT + t] * 0.5f;

        float s = v * v;
        #pragma unroll
        for (int o = 16; o; o >>= 1) s += __shfl_xor_sync(0xffffffffu, s, o);
        if ((t & 31) == 0) ws[t >> 5] = s;
        __syncthreads();
        const float tot = ws[0] + ws[1] + ws[2] + ws[3];
        const float inv = 1.0f / fmaxf(sqrtf(tot), 1e-12f);
        dst[row * FEAT + t] = v * inv;
    } else {
        __syncthreads();
    }
}

// ---------------------------------------------------------------------------
extern "C" void kernel_launch(void* const* d_in, const int* in_sizes, int n_in,
                              void* d_out, int out_size)
{
    const float* feat_s     = (const float*)d_in[0];
    const float* feat_t     = (const float*)d_in[1];
    const void*  idx        = d_in[2];
    const void*  sample_idx = d_in[3];
    const float* mem_s      = (const float*)d_in[4];
    const float* mem_t      = (const float*)d_in[5];
    float* out = (float*)d_out;

    k_build<<<(unsigned)((PER + 255) / 256), 256>>>(sample_idx);

    k_copy_compute<<<CC_BLOCKS, 256>>>((const float4*)mem_s, (const float4*)mem_t,
                                       (float4*)(out + MEM_S_OFF), (float4*)(out + MEM_T_OFF),
                                       (const float4*)feat_s, (const float4*)feat_t, out);

    k_inv<<<1, 32>>>((const float4*)mem_s, (const float4*)mem_t,
                     (const float4*)feat_s, (const float4*)feat_t,
                     sample_idx, out);

    k_epilogue<<<SCALE_BLOCKS + 128, 256>>>(mem_s, mem_t, feat_s, feat_t, idx, out);
}

// round 15
// speedup vs baseline: 1.0131x; 1.0131x over previous
#include <cuda_runtime.h>

// Problem constants (fixed by the reference)
static constexpr int       BS    = 64;
static constexpr int       KP1   = 8193;        // K + 1
static constexpr int       FEAT  = 128;
static constexpr long long NDATA = 1000000LL;
static constexpr float     TINV  = 1.0f / 0.07f;

// d_out layout: out_s | out_t | mem_s_new | mem_t_new  (all float32)
static constexpr long long PER       = (long long)BS * KP1;        // 524,352
static constexpr long long OUT_S_OFF = 0;
static constexpr long long OUT_T_OFF = PER;
static constexpr long long MEM_S_OFF = 2 * PER;
static constexpr long long MEM_T_OFF = MEM_S_OFF + NDATA * FEAT;

// GB300 has 152 SMs (not B300's 148) — size the persistent grid to a whole
// number of blocks per SM or the 16-block SMs become a ~2.6% critical path.
static constexpr int CC_BLOCKS    = 2432;       // 16 x 152
static constexpr int ENT_CAP      = 8;          // bucket capacity per row
static constexpr int OVF_CAP      = 8192;
static constexpr int SCALE_BLOCKS = 513;        // epilogue scale blocks

// g_first word encoding:  count[31:20] | b[19:14] | (k+1)[13:0]
//   count: matches for this row (capped at ENT_CAP on read)
//   (k+1): 1..8193 fits 14 bits; 0 in low 20 bits + count 0 => word 0 = empty
// Bucket entries (slots 1..ENT_CAP-1) use the same (b<<14)|(k+1) encoding.
static constexpr int      CNT_SHIFT = 20;
static constexpr int      B_SHIFT   = 14;
static constexpr unsigned KF_MASK   = (1u << B_SHIFT) - 1u;       // 0x3FFF
static constexpr unsigned ENT_MASK  = (1u << CNT_SHIFT) - 1u;     // 0xFFFFF
static_assert(KP1 <= (int)KF_MASK, "k+1 field too narrow");
static_assert(BS - 1 < (1 << (CNT_SHIFT - B_SHIFT)), "b field too narrow");

__device__ __forceinline__ unsigned enc_entry(unsigned b, unsigned k) {
    return (b << B_SHIFT) | (k + 1u);
}

// Scratch (no device allocations allowed). g_first is self-cleaning: zero at
// module load, re-zeroed by k_copy_compute after consumption each run.
__device__ unsigned g_first[NDATA];             // packed count|entry0
__device__ unsigned g_entries[NDATA * ENT_CAP]; // extra entries (slots 1..7)
__device__ unsigned g_ovf[OVF_CAP];             // overflow: flat sample index i
__device__ unsigned g_ovf_n;                    // reset by k_inv each run
__device__ double   g_sum[2];                   // Z sums (zeroed by k_build)
__device__ float    g_inv[2];                   // final scale factors

// JAX without x64 downcasts the reference's int64 indices to int32.
// Detect from first sample_idx words (true i64 values < 2^31 have zero odd words).
__device__ __forceinline__ bool detect_i64(const int* __restrict__ w) {
    return (w[1] == 0) && (w[3] == 0) && (w[5] == 0) && (w[7] == 0);
}
__device__ __forceinline__ long long load_index(const void* p, long long i, bool i64) {
    return i64 ? ((const long long*)p)[i]
               : (long long)((const int*)p)[i];
}

// Shared dot helper so main and overflow paths are bitwise identical.
__device__ __forceinline__ void dot2_reduce(const float4 vs, const float4 vt,
                                            const float4 ft, const float4 fs,
                                            float& dt, float& ds)
{
    dt = vs.x * ft.x + vs.y * ft.y + vs.z * ft.z + vs.w * ft.w;
    ds = vt.x * fs.x + vt.y * fs.y + vt.z * fs.z + vt.w * fs.w;
    #pragma unroll
    for (int o = 16; o; o >>= 1) {
        dt += __shfl_xor_sync(0xffffffffu, dt, o);
        ds += __shfl_xor_sync(0xffffffffu, ds, o);
    }
}
__device__ __forceinline__ float contrast_val(float d) {
    return __expf(fminf(d * TINV, 50.0f));
}

// Process all matches for one row. w = packed g_first word (count + entry0),
// so the dominant single-match case needs NO second index load. Z accumulates
// on lane 0 only (block reduce reads lane 0's copy).
__device__ __forceinline__ void process_row(
    long long row, unsigned w,
    const float4 vs, const float4 vt,
    const float4* __restrict__ feat_s4, const float4* __restrict__ feat_t4,
    float* __restrict__ out, int lane, double& acc_s, double& acc_t)
{
    unsigned c = w >> CNT_SHIFT;
    c = c < ENT_CAP ? c : ENT_CAP;
    for (unsigned e = 0; e < c; e++) {
        const unsigned ent = (e == 0) ? (w & ENT_MASK)
                                      : g_entries[row * ENT_CAP + e];
        const unsigned b = ent >> B_SHIFT;
        const unsigned k = (ent & KF_MASK) - 1u;
        const float4 ft = feat_t4[b * 32 + lane];
        const float4 fs = feat_s4[b * 32 + lane];
        float dt, ds;
        dot2_reduce(vs, vt, ft, fs, dt, ds);
        const float et = contrast_val(dt);
        const float es = contrast_val(ds);
        if (lane == 0) {
            acc_t += (double)et;
            acc_s += (double)es;
            const long long off = (long long)b * KP1 + k;
            out[OUT_T_OFF + off] = et;
            out[OUT_S_OFF + off] = es;
        }
    }
}

// ---------------------------------------------------------------------------
// Build inverted index. atomicAdd on the count field returns the slot; the
// FIRST arrival also sets the entry bits via atomicOr (disjoint fields;
// k_build completes before any consumer runs). Slots 1..ENT_CAP-1 go to the
// bucket; beyond that, the overflow list. Also zeroes g_sum for this run.
// ---------------------------------------------------------------------------
__global__ void __launch_bounds__(256)
k_build(const void* __restrict__ sample_idx)
{
    if (blockIdx.x == 0 && threadIdx.x == 0) { g_sum[0] = 0.0; g_sum[1] = 0.0; }
    const bool i64 = detect_i64((const int*)sample_idx);
    const long long i = (long long)blockIdx.x * blockDim.x + threadIdx.x;
    if (i >= PER) return;
    const unsigned b = (unsigned)i / (unsigned)KP1;
    const unsigned k = (unsigned)i % (unsigned)KP1;
    const long long r = load_index(sample_idx, i, i64);
    const unsigned old  = atomicAdd(&g_first[r], 1u << CNT_SHIFT);
    const unsigned slot = old >> CNT_SHIFT;
    if (slot == 0) {
        atomicOr(&g_first[r], enc_entry(b, k));
    } else if (slot < ENT_CAP) {
        g_entries[r * ENT_CAP + slot] = enc_entry(b, k);
    } else {
        const unsigned o = atomicAdd(&g_ovf_n, 1u);
        if (o < OVF_CAP) g_ovf[o] = (unsigned)i;
    }
}

// ---------------------------------------------------------------------------
// Copy + contrast + Z-sum, fused. Adjacent 2-row flat batch: 4 stream
// float4s + 2 adjacent g_first words per iteration, all issued before
// stores/match work. Packed word supplies count AND entry0, so single-match
// rows skip the bucket load entirely.
// g_first is zeroed after consumption (self-cleaning for the next run).
// ---------------------------------------------------------------------------
__global__ void __launch_bounds__(256)
k_copy_compute(const float4* __restrict__ mem_s4, const float4* __restrict__ mem_t4,
               float4* __restrict__ dst_s4, float4* __restrict__ dst_t4,
               const float4* __restrict__ feat_s4, const float4* __restrict__ feat_t4,
               float* __restrict__ out)
{
    const int lane = threadIdx.x & 31;
    const int warp = threadIdx.x >> 5;
    const long long warpsTotal = (long long)CC_BLOCKS * 8;          // 19,456
    const long long pairStride = 2 * warpsTotal;
    const long long w0 = (long long)blockIdx.x * 8 + warp;

    double acc_s = 0.0, acc_t = 0.0;            // meaningful on lane 0

    for (long long rowA = w0 * 2; rowA < NDATA; rowA += pairStride) {
        const long long rowB = rowA + 1;
        const bool hasB = (rowB < NDATA);

        // Flat load batch: 4 stream float4s + 2 adjacent packed index words
        const long long baseA = rowA * 32 + lane;
        const float4 vsA = mem_s4[baseA];
        const float4 vtA = mem_t4[baseA];
        float4 vsB, vtB;
        long long baseB = 0;
        if (hasB) {
            baseB = rowB * 32 + lane;
            vsB = mem_s4[baseB];
            vtB = mem_t4[baseB];
        }
        const unsigned wA = g_first[rowA];
        const unsigned wB = hasB ? g_first[rowB] : 0u;

        // Stores
        dst_s4[baseA] = vsA;
        dst_t4[baseA] = vtA;
        if (hasB) {
            dst_s4[baseB] = vsB;
            dst_t4[baseB] = vtB;
        }

        // Self-clean for next run (adjacent words -> one sector)
        if (lane == 0) {
            if (wA) g_first[rowA] = 0u;
            if (wB) g_first[rowB] = 0u;
        }

        // Match work
        if (wA) process_row(rowA, wA, vsA, vtA, feat_s4, feat_t4, out, lane, acc_s, acc_t);
        if (wB) process_row(rowB, wB, vsB, vtB, feat_s4, feat_t4, out, lane, acc_s, acc_t);
    }

    // Block reduce (lane 0 values), then 2 atomics/block
    __shared__ double sh_s[8], sh_t[8];
    if (lane == 0) { sh_s[warp] = acc_s; sh_t[warp] = acc_t; }
    __syncthreads();
    if (threadIdx.x == 0) {
        double ts = 0.0, tt = 0.0;
        #pragma unroll
        for (int i = 0; i < 8; i++) { ts += sh_s[i]; tt += sh_t[i]; }
        atomicAdd(&g_sum[0], ts);
        atomicAdd(&g_sum[1], tt);
    }
}

// ---------------------------------------------------------------------------
// Inv: one warp. Handle the (almost always zero) overflow entries with
// bitwise-identical math, compute scale factors, reset overflow cursor.
// inv = PER / (sum * N_DATA)
// ---------------------------------------------------------------------------
__global__ void __launch_bounds__(32)
k_inv(const float4* __restrict__ mem_s4, const float4* __restrict__ mem_t4,
      const float4* __restrict__ feat_s4, const float4* __restrict__ feat_t4,
      const void* __restrict__ sample_idx, float* __restrict__ out)
{
    const int lane = threadIdx.x;
    double os = 0.0, ot = 0.0;                  // meaningful on lane 0
    const unsigned n = g_ovf_n < OVF_CAP ? g_ovf_n : OVF_CAP;
    if (n) {
        const bool i64 = detect_i64((const int*)sample_idx);
        for (unsigned e = 0; e < n; e++) {
            const long long i = (long long)g_ovf[e];
            const unsigned b = (unsigned)i / (unsigned)KP1;
            const unsigned k = (unsigned)i % (unsigned)KP1;
            const long long row = load_index(sample_idx, i, i64);
            const float4 vs = mem_s4[row * 32 + lane];
            const float4 vt = mem_t4[row * 32 + lane];
            const float4 ft = feat_t4[b * 32 + lane];
            const float4 fs = feat_s4[b * 32 + lane];
            float dt, ds;
            dot2_reduce(vs, vt, ft, fs, dt, ds);
            const float et = contrast_val(dt);
            const float es = contrast_val(ds);
            if (lane == 0) {
                ot += (double)et; os += (double)es;
                const long long off = (long long)b * KP1 + k;
                out[OUT_T_OFF + off] = et;
                out[OUT_S_OFF + off] = es;
            }
        }
    }
    if (lane == 0) {
        const double sum_s = g_sum[0] + os;
        const double sum_t = g_sum[1] + ot;
        g_inv[0] = (float)((double)PER / (sum_s * (double)NDATA));
        g_inv[1] = (float)((double)PER / (sum_t * (double)NDATA));
        g_ovf_n = 0u;                           // reset for next run
    }
}

// ---------------------------------------------------------------------------
// Epilogue: scale (blocks [0, SCALE_BLOCKS), grid-stride ~2 float4/thread)
// + momentum update (last 128 blocks).
// Update: reads ORIGINAL bank, overwrites the copied row in d_out.
// ---------------------------------------------------------------------------
__global__ void __launch_bounds__(256)
k_epilogue(const float* __restrict__ mem_s, const float* __restrict__ mem_t,
           const float* __restrict__ feat_s, const float* __restrict__ feat_t,
           const void*  __restrict__ idx, float* __restrict__ out)
{
    if (blockIdx.x < SCALE_BLOCKS) {
        float4* outv = (float4*)out;
        const long long n4 = 2 * PER / 4;                   // 262,176
        const long long stride = (long long)SCALE_BLOCKS * 256;
        for (long long i = (long long)blockIdx.x * 256 + threadIdx.x;
             i < n4; i += stride) {
            const float inv = g_inv[(i >= PER / 4) ? 1 : 0];
            float4 v = outv[i];
            v.x *= inv; v.y *= inv; v.z *= inv; v.w *= inv;
            outv[i] = v;
        }
        return;
    }

    // Update: 128 work blocks, threads 0..127 active
    const int ub = blockIdx.x - SCALE_BLOCKS;     // [0, 128)
    const int t  = threadIdx.x;
    __shared__ float ws[4];
    if (t < 128) {
        const bool i64 = detect_i64((const int*)idx);
        const int bank = ub >> 6;                 // 0 = s-bank, 1 = t-bank
        const int b    = ub & 63;

        const float* __restrict__ mem  = bank ? mem_t  : mem_s;
        const float* __restrict__ feat = bank ? feat_t : feat_s;
        float* __restrict__ dst = out + (bank ? MEM_T_OFF : MEM_S_OFF);

        const long long row = load_index(idx, b, i64);
        const float v = mem[row * FEAT + t] * 0.5f + feat[(long long)b * FEAT + t] * 0.5f;

        float s = v * v;
        #pragma unroll
        for (int o = 16; o; o >>= 1) s += __shfl_xor_sync(0xffffffffu, s, o);
        if ((t & 31) == 0) ws[t >> 5] = s;
        __syncthreads();
        const float tot = ws[0] + ws[1] + ws[2] + ws[3];
        const float inv = 1.0f / fmaxf(sqrtf(tot), 1e-12f);
        dst[row * FEAT + t] = v * inv;
    } else {
        __syncthreads();
    }
}

// ---------------------------------------------------------------------------
extern "C" void kernel_launch(void* const* d_in, const int* in_sizes, int n_in,
                              void* d_out, int out_size)
{
    const float* feat_s     = (const float*)d_in[0];
    const float* feat_t     = (const float*)d_in[1];
    const void*  idx        = d_in[2];
    const void*  sample_idx = d_in[3];
    const float* mem_s      = (const float*)d_in[4];
    const float* mem_t      = (const float*)d_in[5];
    float* out = (float*)d_out;

    k_build<<<(unsigned)((PER + 255) / 256), 256>>>(sample_idx);

    k_copy_compute<<<CC_BLOCKS, 256>>>((const float4*)mem_s, (const float4*)mem_t,
                                       (float4*)(out + MEM_S_OFF), (float4*)(out + MEM_T_OFF),
                                       (const float4*)feat_s, (const float4*)feat_t, out);

    k_inv<<<1, 32>>>((const float4*)mem_s, (const float4*)mem_t,
                     (const float4*)feat_s, (const float4*)feat_t,
                     sample_idx, out);

    k_epilogue<<<SCALE_BLOCKS + 128, 256>>>(mem_s, mem_t, feat_s, feat_t, idx, out);
}